// round 9
// baseline (speedup 1.0000x reference)
#include <cuda_runtime.h>

// Fan-beam CT forward projector — warp-cooperative gather, 4 bins/warp
// (two bin-pair walks sharing one prologue).
constexpr int   R_      = 384;
constexpr int   C_      = 384;
constexpr int   NCOLS_  = 768;
constexpr int   V_      = 256;
constexpr float DR_     = 1.0f;
constexpr float DC_     = 1.0f;
constexpr float DSPACE_ = 1.5f;

constexpr int WARPS_PER_BLOCK = 4;
constexpr int NQUADS = NCOLS_ / 4;     // 192

struct VG {
    float K, A;
    float bn0, dnr, dnc;
    float bu0, dur, duc;
    float dzx, dzy, sx, sy;
    float ux, uy, rowx, rowy, colx, coly;
};

__device__ __forceinline__ void drive_window(float ahi, float bhi,
                                             float alo, float blo,
                                             int& w0, int& w1)
{
    float f0 = 0.0f, f1 = 383.0f;
    const float eps = 1e-12f;
    if (bhi > eps)        f0 = fmaxf(f0, __fdividef(-0.01f - ahi, bhi) - 1.0f);
    else if (bhi < -eps)  f1 = fminf(f1, __fdividef(-0.01f - ahi, bhi) + 1.0f);
    else if (ahi < -0.01f) { w0 = 1; w1 = 0; return; }
    const float L = 383.01f;
    if (blo > eps)        f1 = fminf(f1, __fdividef(L - alo, blo) + 1.0f);
    else if (blo < -eps)  f0 = fmaxf(f0, __fdividef(L - alo, blo) - 1.0f);
    else if (alo > L)     { w0 = 1; w1 = 0; return; }
    w0 = max(0, __float2int_ru(f0));
    w1 = min(383, __float2int_rd(f1));
}

// One pair-wedge walk. Lanes stride the driving coord s; perp coord p has
// compile-time image stride PSTR; SROW is the complementary stride.
template<int PSTR, int SROW>
__device__ __forceinline__ void walk(const float* __restrict__ img,
                                     int lane,
                                     float q0, float qs, float qp,
                                     float b0, float bs, float bp,
                                     float& acc0, float& acc1)
{
    // wedge lines: Q + B = 0 (col = i-1) and Q - 2B = 0 (col = i+2)
    const float gm  = qp + bp;
    const float gp2 = qp - 2.0f*bp;
    const float am  = __fdividef(-(q0 + b0),      gm);
    const float bm  = __fdividef(-(qs + bs),      gm);
    const float ap  = __fdividef(-(q0 - 2.0f*b0), gp2);
    const float bp3 = __fdividef(-(qs - 2.0f*bs), gp2);
    float alo, blo, ahi, bhi;
    if (fmaf(191.5f, bm, am) <= fmaf(191.5f, bp3, ap)) {
        alo = am; blo = bm; ahi = ap; bhi = bp3;
    } else {
        alo = ap; blo = bp3; ahi = am; bhi = bm;
    }

    int w0i, w1i;
    drive_window(ahi, bhi, alo, blo, w0i, w1i);

    for (int s = w0i + lane; s <= w1i; s += 32) {
        const float sf  = (float)s;
        const float plo = fmaxf(fmaf(sf, blo, alo) - 0.01f, 0.0f);
        const float phi = fminf(fmaf(sf, bhi, ahi) + 0.01f, 383.0f);
        const int p0 = __float2int_ru(plo);
        const int n  = __float2int_rd(phi) - p0;
        if (n >= 0) {
            const float pf0 = (float)p0;
            const float Qb  = fmaf(pf0, qp, fmaf(sf, qs, q0));
            const float Bb  = fmaf(pf0, bp, fmaf(sf, bs, b0));
            const float* p  = img + p0*PSTR + s*SROW;
            #pragma unroll
            for (int k = 0; k < 5; ++k) {
                if (k <= n) {
                    const float Qp = fmaf((float)k, qp, Qb);
                    const float Bp = fmaf((float)k, bp, Bb);
                    const float rb = __fdividef(1.0f, Bp);
                    const float val = __ldg(p + k*PSTR);
                    const float wA = fmaf(-fabsf(Qp), rb, 1.0f);
                    const float wB = fmaf(-fabsf(Qp - Bp), rb, 1.0f);
                    acc0 = fmaf(fmaxf(wA, 0.0f), val, acc0);
                    acc1 = fmaf(fmaxf(wB, 0.0f), val, acc1);
                }
            }
            for (int k = 5; k <= n; ++k) {          // rare tail
                const float Qp = fmaf((float)k, qp, Qb);
                const float Bp = fmaf((float)k, bp, Bb);
                const float rb = __fdividef(1.0f, Bp);
                const float val = __ldg(p + k*PSTR);
                const float wA = fmaf(-fabsf(Qp), rb, 1.0f);
                const float wB = fmaf(-fabsf(Qp - Bp), rb, 1.0f);
                acc0 = fmaf(fmaxf(wA, 0.0f), val, acc0);
                acc1 = fmaf(fmaxf(wB, 0.0f), val, acc1);
            }
        }
    }
}

// Dispatch one pair (bins i, i+1): derive Q coeffs exactly like the reference
// (E = A - i*DS), pick axis, run the templated walk.
__device__ __forceinline__ void do_pair(const float* __restrict__ img,
                                        const VG& g, int lane, int ibin,
                                        float sig, float K,
                                        float b0, float br, float bc,
                                        float& acc0, float& acc1)
{
    const float E  = g.A - (float)ibin * DSPACE_;
    const float q0 = sig * (E*g.bn0 + K*g.bu0);
    const float qr = sig * (E*g.dnr + K*g.dur);
    const float qc = sig * (E*g.dnc + K*g.duc);

    const float ic_f = (float)ibin + 0.5f;
    const float bxp = g.dzx + ic_f*DSPACE_*g.ux - g.sx;
    const float byp = g.dzy + ic_f*DSPACE_*g.uy - g.sy;
    const float dc_comp = bxp*g.colx + byp*g.coly;
    const float dr_comp = bxp*g.rowx + byp*g.rowy;

    if (fabsf(dc_comp) >= fabsf(dr_comp))
        walk<C_, 1>(img, lane, q0, qc, qr, b0, bc, br, acc0, acc1);
    else
        walk<1, C_>(img, lane, q0, qr, qc, b0, br, bc, acc0, acc1);
}

__global__ __launch_bounds__(32 * WARPS_PER_BLOCK, 12)
void fanbeam_fp_kernel(const float* __restrict__ img,
                       const float* __restrict__ src_g,
                       const float* __restrict__ detc_g,
                       const float* __restrict__ u_g,
                       const float* __restrict__ center_g,
                       const float* __restrict__ cdir_g,
                       float* __restrict__ sino)
{
    const int v    = blockIdx.y;
    const int warp = threadIdx.x >> 5;
    const int lane = threadIdx.x & 31;
    const int quad = blockIdx.x * WARPS_PER_BLOCK + warp;   // 0..191
    const int ib   = quad * 4;                              // base bin

    __shared__ VG g;
    if (threadIdx.x == 0) {
        const float sx  = src_g [2*v+0], sy  = src_g [2*v+1];
        const float dcx = detc_g[2*v+0], dcy = detc_g[2*v+1];
        const float ux  = u_g  [2*v+0], uy  = u_g  [2*v+1];
        const float nx  = -uy,          ny  = ux;
        const float cx  = center_g[0],  cy  = center_g[1];
        const float colx = cdir_g[0],   coly = cdir_g[1];
        const float rowx = -coly,       rowy = colx;

        const float vzx = cx - 0.5f*(R_-1)*DR_*rowx - 0.5f*(C_-1)*DC_*colx;
        const float vzy = cy - 0.5f*(R_-1)*DR_*rowy - 0.5f*(C_-1)*DC_*coly;

        const float src_d = sx*nx + sy*ny;
        const float su    = sx*ux + sy*uy;
        const float K     = (dcx*nx + dcy*ny) - src_d;
        const float h     = 0.5f*(NCOLS_-1)*DSPACE_;
        const float dzx   = dcx - h*ux, dzy = dcy - h*uy;
        const float A     = su - (dzx*ux + dzy*uy);

        g.K = K; g.A = A;
        g.bn0 = vzx*nx + vzy*ny - src_d;
        g.dnr = DR_*(rowx*nx + rowy*ny);
        g.dnc = DC_*(colx*nx + coly*ny);
        g.bu0 = vzx*ux + vzy*uy - su;
        g.dur = DR_*(rowx*ux + rowy*uy);
        g.duc = DC_*(colx*ux + coly*uy);
        g.dzx = dzx; g.dzy = dzy; g.sx = sx; g.sy = sy;
        g.ux = ux; g.uy = uy;
        g.rowx = rowx; g.rowy = rowy; g.colx = colx; g.coly = coly;
    }
    __syncthreads();

    const float K = g.K;
    const float den_c = g.bn0 + 0.5f*(R_-1)*g.dnr + 0.5f*(C_-1)*g.dnc;
    const float sig   = (den_c > 0.0f) ? 1.0f : -1.0f;
    const bool  tok   = (sig * K) > 0.0f;

    const float b0 = sig * DSPACE_ * g.bn0;
    const float br = sig * DSPACE_ * g.dnr;
    const float bc = sig * DSPACE_ * g.dnc;

    float a0 = 0.0f, a1 = 0.0f, a2 = 0.0f, a3 = 0.0f;

    if (tok) {
        do_pair(img, g, lane, ib,     sig, K, b0, br, bc, a0, a1);
        do_pair(img, g, lane, ib + 2, sig, K, b0, br, bc, a2, a3);
    }

    #pragma unroll
    for (int off = 16; off > 0; off >>= 1) {
        a0 += __shfl_xor_sync(0xffffffffu, a0, off);
        a1 += __shfl_xor_sync(0xffffffffu, a1, off);
        a2 += __shfl_xor_sync(0xffffffffu, a2, off);
        a3 += __shfl_xor_sync(0xffffffffu, a3, off);
    }

    if (lane == 0) {
        float* o = sino + v*NCOLS_ + ib;
        o[0] = a0; o[1] = a1; o[2] = a2; o[3] = a3;
    }
}

extern "C" void kernel_launch(void* const* d_in, const int* in_sizes, int n_in,
                              void* d_out, int out_size)
{
    const float* img    = (const float*)d_in[0];
    const float* src    = (const float*)d_in[1];
    const float* detc   = (const float*)d_in[2];
    const float* u      = (const float*)d_in[3];
    const float* center = (const float*)d_in[4];
    const float* cdir   = (const float*)d_in[5];
    float* sino = (float*)d_out;

    dim3 grid(NQUADS / WARPS_PER_BLOCK, V_);
    dim3 block(32 * WARPS_PER_BLOCK);
    fanbeam_fp_kernel<<<grid, block>>>(img, src, detc, u, center, cdir, sino);
}